// round 1
// baseline (speedup 1.0000x reference)
#include <cuda_runtime.h>
#include <cstdint>

// Problem constants (match reference)
#define B        4
#define T        1024
#define HALF     256      // VALUE_DIM / 2
#define C        256
#define NLAB     64
#define VDIM     512

// Scratch: A[b][l][d]  (B * NLAB * HALF floats = 65536)
__device__ float g_A[B * NLAB * HALF];

// ---------------------------------------------------------------------------
// Kernel 0: zero scratch A and the output buffer
// ---------------------------------------------------------------------------
__global__ void vb_zero_kernel(float* __restrict__ out) {
    int i = blockIdx.x * blockDim.x + threadIdx.x;
    if (i < B * NLAB * HALF) g_A[i] = 0.0f;
    if (i < B * C) out[i] = 0.0f;
}

// ---------------------------------------------------------------------------
// Kernel 1: scatter-accumulate
//   A[b, label[b,t], d] += score[b,t] * weight[idx[b,t], off + d]
// One warp per (b,t). Each lane handles 8 floats via two float4 ops.
// Vector atomicAdd(float4*) is native on sm_90+.
// ---------------------------------------------------------------------------
__global__ void vb_scatter_kernel(const int*   __restrict__ indices,
                                  const float* __restrict__ scores,
                                  const int*   __restrict__ label,
                                  const int*   __restrict__ index_p,
                                  const float* __restrict__ weight) {
    int gwarp = (blockIdx.x * blockDim.x + threadIdx.x) >> 5;
    int lane  = threadIdx.x & 31;
    if (gwarp >= B * T) return;

    int   idx = indices[gwarp];
    float sc  = scores[gwarp];
    int   lab = label[gwarp];
    int   off = (*index_p == 1) ? HALF : 0;

    const float4* wrow = reinterpret_cast<const float4*>(
        weight + (size_t)idx * VDIM + off);

    float4 v0 = wrow[lane];        // floats [lane*4   .. lane*4+3]
    float4 v1 = wrow[lane + 32];   // floats [128+lane*4 .. ]
    v0.x *= sc; v0.y *= sc; v0.z *= sc; v0.w *= sc;
    v1.x *= sc; v1.y *= sc; v1.z *= sc; v1.w *= sc;

    int b = gwarp >> 10;           // t-major: gwarp = b*T + t
    float4* dst = reinterpret_cast<float4*>(
        g_A + ((size_t)(b * NLAB + lab)) * HALF);

    atomicAdd(dst + lane,      v0);
    atomicAdd(dst + lane + 32, v1);
}

// ---------------------------------------------------------------------------
// Kernel 2: contraction  out[b,c] = sum_{l,d} A[b,l,d] * W[l, off+d, c]
// Grid: (l = 64, dchunk = 4). 256 threads, thread = output column c.
// A chunk (4 x 64) staged in smem; W rows streamed coalesced from L2.
// ---------------------------------------------------------------------------
__global__ void vb_contract_kernel(const float* __restrict__ W,
                                   const int*   __restrict__ index_p,
                                   float*       __restrict__ out) {
    __shared__ float sA[B][64];

    int l  = blockIdx.x;
    int ch = blockIdx.y;          // d-chunk of 64
    int c  = threadIdx.x;         // 0..255

    // Stage A[b, l, ch*64 + dd] for b in 0..3, dd in 0..63
    {
        int b  = threadIdx.x >> 6;
        int dd = threadIdx.x & 63;
        sA[b][dd] = g_A[((size_t)(b * NLAB + l)) * HALF + ch * 64 + dd];
    }
    __syncthreads();

    int off = (*index_p == 1) ? HALF : 0;
    const float* Wbase = W + ((size_t)l * VDIM + off + ch * 64) * C + c;

    float acc0 = 0.f, acc1 = 0.f, acc2 = 0.f, acc3 = 0.f;
#pragma unroll
    for (int d = 0; d < 64; d++) {
        float w = Wbase[(size_t)d * C];   // coalesced across c
        acc0 += sA[0][d] * w;
        acc1 += sA[1][d] * w;
        acc2 += sA[2][d] * w;
        acc3 += sA[3][d] * w;
    }

    atomicAdd(out + 0 * C + c, acc0);
    atomicAdd(out + 1 * C + c, acc1);
    atomicAdd(out + 2 * C + c, acc2);
    atomicAdd(out + 3 * C + c, acc3);
}

// ---------------------------------------------------------------------------
// Launch: inputs in metadata order:
//   0: indices (B,T) int32     1: scores (B,T) f32
//   2: W (64,512,256) f32      3: label (B,T) int32
//   4: index scalar int32      5: weight (262144,512) f32
// Output: (B, C) f32 = 1024 floats
// ---------------------------------------------------------------------------
extern "C" void kernel_launch(void* const* d_in, const int* in_sizes, int n_in,
                              void* d_out, int out_size) {
    const int*   indices = (const int*)  d_in[0];
    const float* scores  = (const float*)d_in[1];
    const float* W       = (const float*)d_in[2];
    const int*   label   = (const int*)  d_in[3];
    const int*   index_p = (const int*)  d_in[4];
    const float* weight  = (const float*)d_in[5];
    float*       out     = (float*)d_out;

    // 0) zero scratch + output  (65536 elements -> 256 blocks x 256)
    vb_zero_kernel<<<256, 256>>>(out);

    // 1) scatter: B*T = 4096 warps -> 131072 threads
    vb_scatter_kernel<<<512, 256>>>(indices, scores, label, index_p, weight);

    // 2) contraction: 64 labels x 4 d-chunks
    dim3 grid(NLAB, 4);
    vb_contract_kernel<<<grid, 256>>>(W, index_p, out);
}